// round 1
// baseline (speedup 1.0000x reference)
#include <cuda_runtime.h>
#include <cuda_bf16.h>

#define Gn 4
#define Nn 50000
#define En 400000
#define Dn 128
#define Ln 3
#define NEx 8
#define AHn 64
#define ROWS (Gn*Nn)
#define LN_EPS 1e-5f

// Scratch (static __device__ arrays — allocation-free per harness rules)
__device__ float g_bufA[(size_t)ROWS * Dn];
__device__ float g_bufB[(size_t)ROWS * Dn];
__device__ float g_hbuf[(size_t)ROWS * Dn];
__device__ float g_gvec[Gn * Dn];

__device__ __forceinline__ const float* pick_src(int s, const float* xin) {
    return s < 0 ? xin : (s == 0 ? g_bufA : g_bufB);
}

// ---------------------------------------------------------------------------
// h = x  (init hbuf before scatter-add so h ends as x + agg)
// ---------------------------------------------------------------------------
__global__ void k_init_h(const float* __restrict__ xin, int xs) {
    const float4* src = (const float4*)pick_src(xs, xin);
    float4* dst = (float4*)g_hbuf;
    size_t i = (size_t)blockIdx.x * blockDim.x + threadIdx.x;
    dst[i] = src[i];   // grid sized exactly
}

// ---------------------------------------------------------------------------
// Edge scatter: h[g][dst] += x[g][src]   (one warp per edge, 128-bit red)
// ---------------------------------------------------------------------------
__global__ void k_scatter(const int* __restrict__ ei, const float* __restrict__ xin, int xs) {
    int wid  = (int)((blockIdx.x * blockDim.x + threadIdx.x) >> 5);
    int lane = threadIdx.x & 31;
    int g = wid / En;
    int e = wid - g * En;
    const int* eig = ei + (size_t)g * 2 * En;
    int s = eig[e];
    int d = eig[En + e];
    const float* x = pick_src(xs, xin);
    float4 v = __ldg((const float4*)(x + ((size_t)g * Nn + s) * Dn) + lane);
    float* h = g_hbuf + ((size_t)g * Nn + d) * Dn + lane * 4;
    unsigned long long ga = __cvta_generic_to_global(h);
    asm volatile("red.global.add.v4.f32 [%0], {%1,%2,%3,%4};"
                 :: "l"(ga), "f"(v.x), "f"(v.y), "f"(v.z), "f"(v.w) : "memory");
}

// ---------------------------------------------------------------------------
// Fused MLP: out = LN( relu(h@W1+b1)@W2 + b2 (+x_id) )
// 64-row tile per block, 256 threads, W1/W2 in smem (160KB dynamic)
// Thread (rg,cg): rows rg*8..+7, cols cg*4..+3
// ---------------------------------------------------------------------------
__global__ void __launch_bounds__(256, 1)
k_mlp(const float* __restrict__ xin, int xs,
      const float* __restrict__ W1, const float* __restrict__ b1,
      const float* __restrict__ W2, const float* __restrict__ b2,
      const float* __restrict__ lng, const float* __restrict__ lnb,
      int addRes, int osel) {
    extern __shared__ float sm[];
    float* W1s = sm;            // 16384 floats
    float* W2s = sm + 16384;    // 16384 floats
    float* As  = sm + 32768;    // 8192 floats (h tile, then reused for relu output)

    int tid = threadIdx.x;
    int cg = tid & 31, rg = tid >> 5;
    int rowbase = blockIdx.x * 64;

    {   // cooperative loads
        const float4* w1g = (const float4*)W1;
        const float4* w2g = (const float4*)W2;
        float4* w1s = (float4*)W1s;
        float4* w2s = (float4*)W2s;
        #pragma unroll 4
        for (int i = tid; i < 4096; i += 256) { w1s[i] = __ldg(w1g + i); w2s[i] = __ldg(w2g + i); }
        const float4* hg = (const float4*)(g_hbuf + (size_t)rowbase * Dn);
        float4* as4 = (float4*)As;
        #pragma unroll 4
        for (int i = tid; i < 2048; i += 256) as4[i] = hg[i];
    }
    __syncthreads();

    float acc[8][4];
    #pragma unroll
    for (int r = 0; r < 8; r++) { acc[r][0]=acc[r][1]=acc[r][2]=acc[r][3]=0.f; }

    // GEMM1
    for (int k0 = 0; k0 < 128; k0 += 4) {
        float4 a4[8];
        #pragma unroll
        for (int r = 0; r < 8; r++) a4[r] = *(float4*)&As[(rg*8+r)*128 + k0];
        #pragma unroll
        for (int kk = 0; kk < 4; kk++) {
            float4 wv = *(float4*)&W1s[(k0+kk)*128 + cg*4];
            #pragma unroll
            for (int r = 0; r < 8; r++) {
                float av = (&a4[r].x)[kk];
                acc[r][0] = fmaf(av, wv.x, acc[r][0]);
                acc[r][1] = fmaf(av, wv.y, acc[r][1]);
                acc[r][2] = fmaf(av, wv.z, acc[r][2]);
                acc[r][3] = fmaf(av, wv.w, acc[r][3]);
            }
        }
    }

    float4 b1v = __ldg((const float4*)b1 + cg);
    __syncthreads();   // all GEMM1 reads of As complete
    #pragma unroll
    for (int r = 0; r < 8; r++) {
        float4 t;
        t.x = fmaxf(acc[r][0] + b1v.x, 0.f);
        t.y = fmaxf(acc[r][1] + b1v.y, 0.f);
        t.z = fmaxf(acc[r][2] + b1v.z, 0.f);
        t.w = fmaxf(acc[r][3] + b1v.w, 0.f);
        *(float4*)&As[(rg*8+r)*128 + cg*4] = t;
    }
    __syncthreads();

    #pragma unroll
    for (int r = 0; r < 8; r++) { acc[r][0]=acc[r][1]=acc[r][2]=acc[r][3]=0.f; }

    // GEMM2
    for (int k0 = 0; k0 < 128; k0 += 4) {
        float4 a4[8];
        #pragma unroll
        for (int r = 0; r < 8; r++) a4[r] = *(float4*)&As[(rg*8+r)*128 + k0];
        #pragma unroll
        for (int kk = 0; kk < 4; kk++) {
            float4 wv = *(float4*)&W2s[(k0+kk)*128 + cg*4];
            #pragma unroll
            for (int r = 0; r < 8; r++) {
                float av = (&a4[r].x)[kk];
                acc[r][0] = fmaf(av, wv.x, acc[r][0]);
                acc[r][1] = fmaf(av, wv.y, acc[r][1]);
                acc[r][2] = fmaf(av, wv.z, acc[r][2]);
                acc[r][3] = fmaf(av, wv.w, acc[r][3]);
            }
        }
    }

    float4 b2v = __ldg((const float4*)b2 + cg);
    float4 gv  = __ldg((const float4*)lng + cg);
    float4 bv  = __ldg((const float4*)lnb + cg);
    const float* xid = pick_src(xs, xin);
    float* out = (osel == 0) ? g_bufA : g_bufB;

    #pragma unroll
    for (int r = 0; r < 8; r++) {
        int row = rowbase + rg*8 + r;
        float4 v;
        v.x = acc[r][0] + b2v.x;
        v.y = acc[r][1] + b2v.y;
        v.z = acc[r][2] + b2v.z;
        v.w = acc[r][3] + b2v.w;
        if (addRes) {
            float4 idv = __ldg((const float4*)(xid + (size_t)row * Dn) + cg);
            v.x += idv.x; v.y += idv.y; v.z += idv.z; v.w += idv.w;
        }
        float s  = v.x + v.y + v.z + v.w;
        float ss = v.x*v.x + v.y*v.y + v.z*v.z + v.w*v.w;
        #pragma unroll
        for (int o = 16; o > 0; o >>= 1) {
            s  += __shfl_xor_sync(0xffffffffu, s,  o);
            ss += __shfl_xor_sync(0xffffffffu, ss, o);
        }
        float mu  = s * (1.f / 128.f);
        float var = ss * (1.f / 128.f) - mu * mu;
        float inv = rsqrtf(var + LN_EPS);
        float4 ov;
        ov.x = (v.x - mu) * inv * gv.x + bv.x;
        ov.y = (v.y - mu) * inv * gv.y + bv.y;
        ov.z = (v.z - mu) * inv * gv.z + bv.z;
        ov.w = (v.w - mu) * inv * gv.w + bv.w;
        *(float4*)(out + (size_t)row * Dn + cg * 4) = ov;
    }
}

// ---------------------------------------------------------------------------
// Readout: gvec[g] = sum over nodes
// ---------------------------------------------------------------------------
__global__ void k_zero() { g_gvec[threadIdx.x] = 0.f; }

__global__ void k_readout(int xs) {
    const float* x = (xs == 0) ? g_bufA : g_bufB;
    int g = blockIdx.x;
    int chunk = blockIdx.y;
    int d = threadIdx.x;           // 128 threads
    int i0 = chunk * 1563;
    int i1 = min(Nn, i0 + 1563);
    float s = 0.f;
    const float* base = x + (size_t)g * Nn * Dn + d;
    for (int i = i0; i < i1; i++) s += __ldg(base + (size_t)i * Dn);
    atomicAdd(&g_gvec[g * Dn + d], s);
}

// ---------------------------------------------------------------------------
// Attention pooling: tiny, single block
// ---------------------------------------------------------------------------
__global__ void k_att(const float* __restrict__ w1, const float* __restrict__ w2,
                      float* __restrict__ out) {
    __shared__ float gm[Gn * Dn];   // 512
    __shared__ float sup[AHn * Gn]; // 256 : [ah][gr]
    __shared__ float att[NEx * Gn]; // 32  : [e][gr]
    int tid = threadIdx.x;          // 256
    for (int i = tid; i < Gn * Dn; i += 256) gm[i] = g_gvec[i];
    __syncthreads();
    if (tid < AHn * Gn) {
        int ah = tid >> 2, gr = tid & 3;
        float s = 0.f;
        #pragma unroll 8
        for (int d = 0; d < Dn; d++) s = fmaf(__ldg(w1 + ah * Dn + d), gm[gr * Dn + d], s);
        sup[tid] = tanhf(s);
    }
    __syncthreads();
    if (tid < NEx * Gn) {
        int e = tid >> 2, gr = tid & 3;
        float s = 0.f;
        #pragma unroll 8
        for (int a = 0; a < AHn; a++) s = fmaf(__ldg(w2 + e * AHn + a), sup[a * 4 + gr], s);
        att[tid] = s;
    }
    __syncthreads();
    if (tid < NEx) {
        float m = -1e30f;
        #pragma unroll
        for (int gr = 0; gr < 4; gr++) m = fmaxf(m, att[tid * 4 + gr]);
        float ex[4]; float sum = 0.f;
        #pragma unroll
        for (int gr = 0; gr < 4; gr++) { ex[gr] = expf(att[tid * 4 + gr] - m); sum += ex[gr]; }
        float inv = 1.f / sum;
        #pragma unroll
        for (int gr = 0; gr < 4; gr++) att[tid * 4 + gr] = ex[gr] * inv;
    }
    __syncthreads();
    for (int o = tid; o < NEx * Dn; o += 256) {
        int e = o >> 7, d = o & 127;
        float s = 0.f;
        #pragma unroll
        for (int gr = 0; gr < 4; gr++) s = fmaf(att[e * 4 + gr], gm[gr * Dn + d], s);
        out[o] = s;
    }
}

// ---------------------------------------------------------------------------
extern "C" void kernel_launch(void* const* d_in, const int* in_sizes, int n_in,
                              void* d_out, int out_size) {
    const float* x0  = (const float*)d_in[0];
    const int*   ei  = (const int*)d_in[1];
    // d_in[2] = edge_attr (unused by the GIN path)
    const float* Ws1 = (const float*)d_in[3];
    const float* bs1 = (const float*)d_in[4];
    const float* Ws2 = (const float*)d_in[5];
    const float* bs2 = (const float*)d_in[6];
    const float* lng = (const float*)d_in[7];
    const float* lnb = (const float*)d_in[8];
    const float* aw1 = (const float*)d_in[9];
    const float* aw2 = (const float*)d_in[10];
    float* out = (float*)d_out;

    const int SMEM = (16384 + 16384 + 8192) * sizeof(float);  // 160 KB
    cudaFuncSetAttribute(k_mlp, cudaFuncAttributeMaxDynamicSharedMemorySize, SMEM);

    int xs = -1;  // -1: input, 0: bufA, 1: bufB
    for (int l = 0; l < Ln; l++) {
        k_init_h<<<(ROWS * Dn / 4) / 256, 256>>>(x0, xs);
        k_scatter<<<(Gn * En) / 8, 256>>>(ei, x0, xs);
        int osel = (l == 1) ? 1 : 0;   // l0->A, l1->B, l2->A
        k_mlp<<<ROWS / 64, 256, SMEM>>>(x0, xs,
                                        Ws1 + (size_t)l * Dn * Dn, bs1 + l * Dn,
                                        Ws2 + (size_t)l * Dn * Dn, bs2 + l * Dn,
                                        lng + l * Dn, lnb + l * Dn,
                                        (l < Ln - 1) ? 1 : 0, osel);
        xs = osel;
    }
    k_zero<<<1, Gn * Dn>>>();
    k_readout<<<dim3(Gn, 32), Dn>>>(xs);
    k_att<<<1, 256>>>(aw1, aw2, out);
}

// round 4
// speedup vs baseline: 1.5997x; 1.5997x over previous
#include <cuda_runtime.h>
#include <cstdint>

#define Gn 4
#define Nn 50000
#define En 400000
#define Dn 128
#define Ln 3
#define NEx 8
#define AHn 64
#define ROWS (Gn*Nn)
#define NT128 ((ROWS + 127) / 128)
#define LN_EPS 1e-5f

// ---------------- scratch (static, allocation-free) ----------------
__device__ float g_bufA[(size_t)ROWS * Dn];
__device__ float g_bufB[(size_t)ROWS * Dn];
__device__ float g_hbuf[(size_t)ROWS * Dn];
__device__ float g_gvec[Gn * Dn];
// fragment-linear tf32 weight images: per layer 16384 floats each
__device__ float g_W1p[Ln * Dn * Dn];
__device__ float g_W2p[Ln * Dn * Dn];

__device__ __forceinline__ const float* pick_src(int s, const float* xin) {
    return s < 0 ? xin : (s == 0 ? g_bufA : g_bufB);
}
__device__ __forceinline__ float to_tf32(float v) {
    float o;
    asm("cvt.rna.tf32.f32 %0, %1;" : "=f"(o) : "f"(v));
    return o;
}
__device__ __forceinline__ void mma_tf32(float* c, uint32_t a0, uint32_t a1,
                                         uint32_t a2, uint32_t a3,
                                         uint32_t b0, uint32_t b1) {
    asm volatile(
        "mma.sync.aligned.m16n8k8.row.col.f32.tf32.tf32.f32 "
        "{%0,%1,%2,%3}, {%4,%5,%6,%7}, {%8,%9}, {%0,%1,%2,%3};"
        : "+f"(c[0]), "+f"(c[1]), "+f"(c[2]), "+f"(c[3])
        : "r"(a0), "r"(a1), "r"(a2), "r"(a3), "r"(b0), "r"(b1));
}

// ---------------- simple kernels (unchanged from passing R1) ----------------
__global__ void k_init_h(const float* __restrict__ xin, int xs) {
    const float4* src = (const float4*)pick_src(xs, xin);
    float4* dst = (float4*)g_hbuf;
    size_t i = (size_t)blockIdx.x * blockDim.x + threadIdx.x;
    dst[i] = src[i];
}

__global__ void k_scatter(const int* __restrict__ ei, const float* __restrict__ xin, int xs) {
    int wid  = (int)((blockIdx.x * blockDim.x + threadIdx.x) >> 5);
    int lane = threadIdx.x & 31;
    int g = wid / En;
    int e = wid - g * En;
    const int* eig = ei + (size_t)g * 2 * En;
    int s = eig[e];
    int d = eig[En + e];
    const float* x = pick_src(xs, xin);
    float4 v = __ldg((const float4*)(x + ((size_t)g * Nn + s) * Dn) + lane);
    float* h = g_hbuf + ((size_t)g * Nn + d) * Dn + lane * 4;
    unsigned long long ga = __cvta_generic_to_global(h);
    asm volatile("red.global.add.v4.f32 [%0], {%1,%2,%3,%4};"
                 :: "l"(ga), "f"(v.x), "f"(v.y), "f"(v.z), "f"(v.w) : "memory");
}

// ---------------- weight pre-pack into mma fragment order ----------------
// Mainloop load: float4 at wf[(kt*8+np)*32 + lane] gives, for n-tiles
// nt=2np and 2np+1: {b0(nt), b1(nt), b0(nt+1), b1(nt+1)} with
// b0 = W[kt*8+tig][nt*8+g], b1 = W[kt*8+tig+4][nt*8+g]  (lane = g*4+tig)
__global__ void k_pack(const float* __restrict__ Ws1, const float* __restrict__ Ws2) {
    int idx = blockIdx.x * 256 + threadIdx.x;
    if (idx >= Ln * Dn * Dn) return;
    int l = idx / 16384, r = idx % 16384;
    int kt = r >> 10, np = (r >> 7) & 7, lane = (r >> 2) & 31, j = r & 3;
    int g = lane >> 2, tig = lane & 3;
    int nt = np * 2 + (j >> 1);
    int krow = kt * 8 + tig + ((j & 1) ? 4 : 0);
    int ncol = nt * 8 + g;
    size_t src = ((size_t)l * Dn + krow) * Dn + ncol;
    g_W1p[idx] = to_tf32(Ws1[src]);
    g_W2p[idx] = to_tf32(Ws2[src]);
}

// ---------------- fused MLP via mma.sync tf32 ----------------
// smem map (bytes):
//   [0, 2048)            b1,b2,lng,lnb (4 x 128 floats)
//   [2048, 67584)        W1 frags (16384 floats, 64KB)
//   [67584, 133120)      W2 frags (16384 floats, 64KB)
//   [133120, 200704)     A tile 128 x 132 floats
#define AS_STRIDE 132
#define SM_TOT (2048 + 65536 + 65536 + 128*AS_STRIDE*4)   // 200704

__global__ void __launch_bounds__(256, 1)
k_mlp_mma(const float* __restrict__ xin, int xs, int layer,
          const float* __restrict__ b1, const float* __restrict__ b2,
          const float* __restrict__ lng, const float* __restrict__ lnb,
          int addRes, int osel) {
    extern __shared__ float sm[];
    float* b1s  = sm;
    float* b2s  = sm + 128;
    float* lngs = sm + 256;
    float* lnbs = sm + 384;
    float* wf1  = sm + 512;            // 16384 floats
    float* wf2  = wf1 + 16384;         // 16384 floats  (FIX: was +8192)
    float* As   = wf2 + 16384;         // 128*132 floats

    int tid = threadIdx.x;
    int wid = tid >> 5, lane = tid & 31;
    int g = lane >> 2, tig = lane & 3;

    {   // preload weights + vectors
        const float4* w1g = (const float4*)(g_W1p + (size_t)layer * 16384);
        const float4* w2g = (const float4*)(g_W2p + (size_t)layer * 16384);
        float4* w1s = (float4*)wf1;
        float4* w2s = (float4*)wf2;
        #pragma unroll 4
        for (int i = tid; i < 4096; i += 256) { w1s[i] = __ldg(w1g + i); w2s[i] = __ldg(w2g + i); }
        if (tid < 128) {
            b1s[tid]  = __ldg(b1 + tid);
            b2s[tid]  = __ldg(b2 + tid);
            lngs[tid] = __ldg(lng + tid);
            lnbs[tid] = __ldg(lnb + tid);
        }
    }
    __syncthreads();

    const float* xid = pick_src(xs, xin);
    float* out = (osel == 0) ? g_bufA : g_bufB;

    // per-thread A-frag row pointers (warp owns rows [wid*16, wid*16+16))
    float* rp0 = As + (wid * 16 + g) * AS_STRIDE;
    float* rp1 = rp0 + 8 * AS_STRIDE;

    float acc[16][4];

    for (int tile = blockIdx.x; tile < NT128; tile += gridDim.x) {
        int rowbase = tile * 128;
        int wrow = rowbase + wid * 16;

        // ---- fill own 16 rows of A (tf32-rounded); lane = float4 column
        {
            float* arow = As + wid * 16 * AS_STRIDE;
            #pragma unroll
            for (int i = 0; i < 16; i++) {
                float4 v = make_float4(0.f, 0.f, 0.f, 0.f);
                if (wrow + i < ROWS)
                    v = *(const float4*)(g_hbuf + (size_t)(wrow + i) * Dn + lane * 4);
                v.x = to_tf32(v.x); v.y = to_tf32(v.y);
                v.z = to_tf32(v.z); v.w = to_tf32(v.w);
                *(float4*)&arow[i * AS_STRIDE + lane * 4] = v;
            }
        }
        __syncwarp();

        // ---- GEMM1: 16x128 @ 128x128
        #pragma unroll
        for (int nt = 0; nt < 16; nt++) { acc[nt][0]=acc[nt][1]=acc[nt][2]=acc[nt][3]=0.f; }
        #pragma unroll
        for (int kt = 0; kt < 16; kt++) {
            uint32_t a0 = __float_as_uint(rp0[kt*8 + tig]);
            uint32_t a1 = __float_as_uint(rp1[kt*8 + tig]);
            uint32_t a2 = __float_as_uint(rp0[kt*8 + tig + 4]);
            uint32_t a3 = __float_as_uint(rp1[kt*8 + tig + 4]);
            const float4* wfb = (const float4*)wf1 + kt * 8 * 32 + lane;
            #pragma unroll
            for (int np = 0; np < 8; np++) {
                float4 b = wfb[np * 32];
                mma_tf32(acc[2*np],   a0, a1, a2, a3, __float_as_uint(b.x), __float_as_uint(b.y));
                mma_tf32(acc[2*np+1], a0, a1, a2, a3, __float_as_uint(b.z), __float_as_uint(b.w));
            }
        }

        // ---- relu(+b1), tf32, stage back into own A rows
        __syncwarp();
        #pragma unroll
        for (int nt = 0; nt < 16; nt++) {
            float2 bb = *(float2*)&b1s[nt*8 + tig*2];
            float2 lo, hi;
            lo.x = to_tf32(fmaxf(acc[nt][0] + bb.x, 0.f));
            lo.y = to_tf32(fmaxf(acc[nt][1] + bb.y, 0.f));
            hi.x = to_tf32(fmaxf(acc[nt][2] + bb.x, 0.f));
            hi.y = to_tf32(fmaxf(acc[nt][3] + bb.y, 0.f));
            *(float2*)&rp0[nt*8 + tig*2] = lo;
            *(float2*)&rp1[nt*8 + tig*2] = hi;
        }
        __syncwarp();

        // ---- GEMM2
        #pragma unroll
        for (int nt = 0; nt < 16; nt++) { acc[nt][0]=acc[nt][1]=acc[nt][2]=acc[nt][3]=0.f; }
        #pragma unroll
        for (int kt = 0; kt < 16; kt++) {
            uint32_t a0 = __float_as_uint(rp0[kt*8 + tig]);
            uint32_t a1 = __float_as_uint(rp1[kt*8 + tig]);
            uint32_t a2 = __float_as_uint(rp0[kt*8 + tig + 4]);
            uint32_t a3 = __float_as_uint(rp1[kt*8 + tig + 4]);
            const float4* wfb = (const float4*)wf2 + kt * 8 * 32 + lane;
            #pragma unroll
            for (int np = 0; np < 8; np++) {
                float4 b = wfb[np * 32];
                mma_tf32(acc[2*np],   a0, a1, a2, a3, __float_as_uint(b.x), __float_as_uint(b.y));
                mma_tf32(acc[2*np+1], a0, a1, a2, a3, __float_as_uint(b.z), __float_as_uint(b.w));
            }
        }

        // ---- epilogue: +b2 (+residual), LN over quad, store
        {
            int r0g = wrow + g, r1g = wrow + g + 8;
            bool v0 = r0g < ROWS, v1 = r1g < ROWS;
            const float* res0 = xid + (size_t)r0g * Dn;
            const float* res1 = xid + (size_t)r1g * Dn;
            float s0 = 0.f, ss0 = 0.f, s1 = 0.f, ss1 = 0.f;
            #pragma unroll
            for (int nt = 0; nt < 16; nt++) {
                int c = nt*8 + tig*2;
                float2 bb = *(float2*)&b2s[c];
                acc[nt][0] += bb.x; acc[nt][1] += bb.y;
                acc[nt][2] += bb.x; acc[nt][3] += bb.y;
                if (addRes) {
                    if (v0) { float2 rv = __ldg((const float2*)(res0 + c));
                              acc[nt][0] += rv.x; acc[nt][1] += rv.y; }
                    if (v1) { float2 rv = __ldg((const float2*)(res1 + c));
                              acc[nt][2] += rv.x; acc[nt][3] += rv.y; }
                }
                s0  += acc[nt][0] + acc[nt][1];
                ss0 += acc[nt][0]*acc[nt][0] + acc[nt][1]*acc[nt][1];
                s1  += acc[nt][2] + acc[nt][3];
                ss1 += acc[nt][2]*acc[nt][2] + acc[nt][3]*acc[nt][3];
            }
            // quad reduce (row r0g lives in lanes g*4..g*4+3)
            s0  += __shfl_xor_sync(0xffffffffu, s0, 1);  s0  += __shfl_xor_sync(0xffffffffu, s0, 2);
            ss0 += __shfl_xor_sync(0xffffffffu, ss0, 1); ss0 += __shfl_xor_sync(0xffffffffu, ss0, 2);
            s1  += __shfl_xor_sync(0xffffffffu, s1, 1);  s1  += __shfl_xor_sync(0xffffffffu, s1, 2);
            ss1 += __shfl_xor_sync(0xffffffffu, ss1, 1); ss1 += __shfl_xor_sync(0xffffffffu, ss1, 2);
            float mu0 = s0 * (1.f/128.f), mu1 = s1 * (1.f/128.f);
            float iv0 = rsqrtf(ss0 * (1.f/128.f) - mu0*mu0 + LN_EPS);
            float iv1 = rsqrtf(ss1 * (1.f/128.f) - mu1*mu1 + LN_EPS);
            float* o0 = out + (size_t)r0g * Dn;
            float* o1 = out + (size_t)r1g * Dn;
            #pragma unroll
            for (int nt = 0; nt < 16; nt++) {
                int c = nt*8 + tig*2;
                float2 gg = *(float2*)&lngs[c];
                float2 bb = *(float2*)&lnbs[c];
                if (v0) {
                    float2 ov;
                    ov.x = (acc[nt][0] - mu0) * iv0 * gg.x + bb.x;
                    ov.y = (acc[nt][1] - mu0) * iv0 * gg.y + bb.y;
                    *(float2*)(o0 + c) = ov;
                }
                if (v1) {
                    float2 ov;
                    ov.x = (acc[nt][2] - mu1) * iv1 * gg.x + bb.x;
                    ov.y = (acc[nt][3] - mu1) * iv1 * gg.y + bb.y;
                    *(float2*)(o1 + c) = ov;
                }
            }
        }
        __syncwarp();
    }
}

// ---------------- readout + attention ----------------
__global__ void k_zero() { g_gvec[threadIdx.x] = 0.f; }

__global__ void k_readout(int xs) {
    const float* x = (xs == 0) ? g_bufA : g_bufB;
    int g = blockIdx.x;
    int chunk = blockIdx.y;
    int d = threadIdx.x;
    int i0 = chunk * 1563;
    int i1 = min(Nn, i0 + 1563);
    float s = 0.f;
    const float* base = x + (size_t)g * Nn * Dn + d;
    for (int i = i0; i < i1; i++) s += __ldg(base + (size_t)i * Dn);
    atomicAdd(&g_gvec[g * Dn + d], s);
}

__global__ void k_att(const float* __restrict__ w1, const float* __restrict__ w2,
                      float* __restrict__ out) {
    __shared__ float gm[Gn * Dn];
    __shared__ float sup[AHn * Gn];
    __shared__ float att[NEx * Gn];
    int tid = threadIdx.x;
    for (int i = tid; i < Gn * Dn; i += 256) gm[i] = g_gvec[i];
    __syncthreads();
    if (tid < AHn * Gn) {
        int ah = tid >> 2, gr = tid & 3;
        float s = 0.f;
        #pragma unroll 8
        for (int d = 0; d < Dn; d++) s = fmaf(__ldg(w1 + ah * Dn + d), gm[gr * Dn + d], s);
        sup[tid] = tanhf(s);
    }
    __syncthreads();
    if (tid < NEx * Gn) {
        int e = tid >> 2, gr = tid & 3;
        float s = 0.f;
        #pragma unroll 8
        for (int a = 0; a < AHn; a++) s = fmaf(__ldg(w2 + e * AHn + a), sup[a * 4 + gr], s);
        att[tid] = s;
    }
    __syncthreads();
    if (tid < NEx) {
        float m = -1e30f;
        #pragma unroll
        for (int gr = 0; gr < 4; gr++) m = fmaxf(m, att[tid * 4 + gr]);
        float ex[4]; float sum = 0.f;
        #pragma unroll
        for (int gr = 0; gr < 4; gr++) { ex[gr] = expf(att[tid * 4 + gr] - m); sum += ex[gr]; }
        float inv = 1.f / sum;
        #pragma unroll
        for (int gr = 0; gr < 4; gr++) att[tid * 4 + gr] = ex[gr] * inv;
    }
    __syncthreads();
    for (int o = tid; o < NEx * Dn; o += 256) {
        int e = o >> 7, d = o & 127;
        float s = 0.f;
        #pragma unroll
        for (int gr = 0; gr < 4; gr++) s = fmaf(att[e * 4 + gr], gm[gr * Dn + d], s);
        out[o] = s;
    }
}

// ---------------------------------------------------------------------------
extern "C" void kernel_launch(void* const* d_in, const int* in_sizes, int n_in,
                              void* d_out, int out_size) {
    const float* x0  = (const float*)d_in[0];
    const int*   ei  = (const int*)d_in[1];
    const float* Ws1 = (const float*)d_in[3];
    const float* bs1 = (const float*)d_in[4];
    const float* Ws2 = (const float*)d_in[5];
    const float* bs2 = (const float*)d_in[6];
    const float* lng = (const float*)d_in[7];
    const float* lnb = (const float*)d_in[8];
    const float* aw1 = (const float*)d_in[9];
    const float* aw2 = (const float*)d_in[10];
    float* out = (float*)d_out;

    cudaFuncSetAttribute(k_mlp_mma, cudaFuncAttributeMaxDynamicSharedMemorySize, SM_TOT);

    k_pack<<<(Ln * Dn * Dn + 255) / 256, 256>>>(Ws1, Ws2);

    int xs = -1;  // -1: input, 0: bufA, 1: bufB
    for (int l = 0; l < Ln; l++) {
        k_init_h<<<(ROWS * Dn / 4) / 256, 256>>>(x0, xs);
        k_scatter<<<(Gn * En) / 8, 256>>>(ei, x0, xs);
        int osel = (l == 1) ? 1 : 0;
        k_mlp_mma<<<148, 256, SM_TOT>>>(x0, xs, l,
                                        bs1 + l * Dn, bs2 + l * Dn,
                                        lng + l * Dn, lnb + l * Dn,
                                        (l < Ln - 1) ? 1 : 0, osel);
        xs = osel;
    }
    k_zero<<<1, Gn * Dn>>>();
    k_readout<<<dim3(Gn, 32), Dn>>>(xs);
    k_att<<<1, 256>>>(aw1, aw2, out);
}

// round 5
// speedup vs baseline: 2.2970x; 1.4358x over previous
#include <cuda_runtime.h>
#include <cstdint>

#define Gn 4
#define Nn 50000
#define En 400000
#define Dn 128
#define Ln 3
#define NEx 8
#define AHn 64
#define ROWS (Gn*Nn)
#define EDGES (Gn*En)
#define NT128 ((ROWS + 127) / 128)
#define LN_EPS 1e-5f
#define NB_SCAN 782              // ceil(ROWS/256)

// ---------------- scratch (static, allocation-free) ----------------
__device__ float g_bufA[(size_t)ROWS * Dn];
__device__ float g_bufB[(size_t)ROWS * Dn];
__device__ float g_hbuf[(size_t)ROWS * Dn];
__device__ float g_gvec[Gn * Dn];
__device__ float g_W1p[Ln * Dn * Dn];
__device__ float g_W2p[Ln * Dn * Dn];
// CSR scratch
__device__ int g_cnt[ROWS];
__device__ int g_off[ROWS];
__device__ int g_cur[ROWS];
__device__ int g_adj[EDGES];
__device__ int g_bsum[NB_SCAN];

__device__ __forceinline__ const float* pick_src(int s, const float* xin) {
    return s < 0 ? xin : (s == 0 ? g_bufA : g_bufB);
}
__device__ __forceinline__ float to_tf32(float v) {
    float o;
    asm("cvt.rna.tf32.f32 %0, %1;" : "=f"(o) : "f"(v));
    return o;
}
__device__ __forceinline__ void mma_tf32(float* c, uint32_t a0, uint32_t a1,
                                         uint32_t a2, uint32_t a3,
                                         uint32_t b0, uint32_t b1) {
    asm volatile(
        "mma.sync.aligned.m16n8k8.row.col.f32.tf32.tf32.f32 "
        "{%0,%1,%2,%3}, {%4,%5,%6,%7}, {%8,%9}, {%0,%1,%2,%3};"
        : "+f"(c[0]), "+f"(c[1]), "+f"(c[2]), "+f"(c[3])
        : "r"(a0), "r"(a1), "r"(a2), "r"(a3), "r"(b0), "r"(b1));
}

// ---------------- CSR build (edge index is launch-constant) ----------------
__global__ void k_csr_zero() {
    int i = blockIdx.x * 256 + threadIdx.x;
    if (i < ROWS) g_cnt[i] = 0;
}

__global__ void k_csr_count(const int* __restrict__ ei) {
    int t = blockIdx.x * 256 + threadIdx.x;   // t < EDGES exactly
    int g = t / En, e = t - g * En;
    int dst = ei[(size_t)g * 2 * En + En + e];
    atomicAdd(&g_cnt[g * Nn + dst], 1);
}

__global__ void k_scan_block() {
    __shared__ int s[256];
    int i = blockIdx.x * 256 + threadIdx.x;
    int v = (i < ROWS) ? g_cnt[i] : 0;
    s[threadIdx.x] = v;
    __syncthreads();
    #pragma unroll
    for (int o = 1; o < 256; o <<= 1) {
        int t = (threadIdx.x >= o) ? s[threadIdx.x - o] : 0;
        __syncthreads();
        s[threadIdx.x] += t;
        __syncthreads();
    }
    if (i < ROWS) g_off[i] = s[threadIdx.x] - v;   // exclusive within block
    if (threadIdx.x == 255) g_bsum[blockIdx.x] = s[255];
}

__global__ void k_scan_top() {   // single block, 1024 threads
    __shared__ int s[1024];
    int tid = threadIdx.x;
    int v = (tid < NB_SCAN) ? g_bsum[tid] : 0;
    s[tid] = v;
    __syncthreads();
    #pragma unroll
    for (int o = 1; o < 1024; o <<= 1) {
        int t = (tid >= o) ? s[tid - o] : 0;
        __syncthreads();
        s[tid] += t;
        __syncthreads();
    }
    if (tid < NB_SCAN) g_bsum[tid] = s[tid] - v;   // exclusive
}

__global__ void k_scan_add() {
    int i = blockIdx.x * 256 + threadIdx.x;
    if (i < ROWS) {
        int o = g_off[i] + g_bsum[blockIdx.x];
        g_off[i] = o;
        g_cur[i] = o;
    }
}

__global__ void k_csr_fill(const int* __restrict__ ei) {
    int t = blockIdx.x * 256 + threadIdx.x;
    int g = t / En, e = t - g * En;
    const int* eig = ei + (size_t)g * 2 * En;
    int src = eig[e];
    int dst = eig[En + e];
    int pos = atomicAdd(&g_cur[g * Nn + dst], 1);
    g_adj[pos] = g * Nn + src;
}

// ---------------- gather-only aggregation: h = x + sum_{j->i} x[j] --------
__global__ void k_agg(const float* __restrict__ xin, int xs) {
    int w = (int)((blockIdx.x * blockDim.x + threadIdx.x) >> 5);   // node row
    int lane = threadIdx.x & 31;
    const float* x = pick_src(xs, xin);
    int base = g_off[w];
    int end = (w == ROWS - 1) ? EDGES : g_off[w + 1];
    float4 acc = __ldg((const float4*)(x + (size_t)w * Dn) + lane);
    for (int j0 = base; j0 < end; j0 += 32) {
        int n = end - j0;
        int sv = (lane < n) ? g_adj[j0 + lane] : 0;
        int m = min(n, 32);
        int k = 0;
        for (; k + 4 <= m; k += 4) {   // MLP=4 gather pipeline
            int s0 = __shfl_sync(0xffffffffu, sv, k);
            int s1 = __shfl_sync(0xffffffffu, sv, k + 1);
            int s2 = __shfl_sync(0xffffffffu, sv, k + 2);
            int s3 = __shfl_sync(0xffffffffu, sv, k + 3);
            float4 v0 = __ldg((const float4*)(x + (size_t)s0 * Dn) + lane);
            float4 v1 = __ldg((const float4*)(x + (size_t)s1 * Dn) + lane);
            float4 v2 = __ldg((const float4*)(x + (size_t)s2 * Dn) + lane);
            float4 v3 = __ldg((const float4*)(x + (size_t)s3 * Dn) + lane);
            acc.x += v0.x + v1.x + v2.x + v3.x;
            acc.y += v0.y + v1.y + v2.y + v3.y;
            acc.z += v0.z + v1.z + v2.z + v3.z;
            acc.w += v0.w + v1.w + v2.w + v3.w;
        }
        for (; k < m; k++) {
            int s0 = __shfl_sync(0xffffffffu, sv, k);
            float4 v0 = __ldg((const float4*)(x + (size_t)s0 * Dn) + lane);
            acc.x += v0.x; acc.y += v0.y; acc.z += v0.z; acc.w += v0.w;
        }
    }
    *((float4*)(g_hbuf + (size_t)w * Dn) + lane) = acc;
}

// ---------------- weight pre-pack into mma fragment order ----------------
__global__ void k_pack(const float* __restrict__ Ws1, const float* __restrict__ Ws2) {
    int idx = blockIdx.x * 256 + threadIdx.x;
    if (idx >= Ln * Dn * Dn) return;
    int l = idx / 16384, r = idx % 16384;
    int kt = r >> 10, np = (r >> 7) & 7, lane = (r >> 2) & 31, j = r & 3;
    int g = lane >> 2, tig = lane & 3;
    int nt = np * 2 + (j >> 1);
    int krow = kt * 8 + tig + ((j & 1) ? 4 : 0);
    int ncol = nt * 8 + g;
    size_t src = ((size_t)l * Dn + krow) * Dn + ncol;
    g_W1p[idx] = to_tf32(Ws1[src]);
    g_W2p[idx] = to_tf32(Ws2[src]);
}

// ---------------- fused MLP via mma.sync tf32 (unchanged from R4) ---------
#define AS_STRIDE 132
#define SM_TOT (2048 + 65536 + 65536 + 128*AS_STRIDE*4)   // 200704

__global__ void __launch_bounds__(256, 1)
k_mlp_mma(const float* __restrict__ xin, int xs, int layer,
          const float* __restrict__ b1, const float* __restrict__ b2,
          const float* __restrict__ lng, const float* __restrict__ lnb,
          int addRes, int osel) {
    extern __shared__ float sm[];
    float* b1s  = sm;
    float* b2s  = sm + 128;
    float* lngs = sm + 256;
    float* lnbs = sm + 384;
    float* wf1  = sm + 512;
    float* wf2  = wf1 + 16384;
    float* As   = wf2 + 16384;

    int tid = threadIdx.x;
    int wid = tid >> 5, lane = tid & 31;
    int g = lane >> 2, tig = lane & 3;

    {
        const float4* w1g = (const float4*)(g_W1p + (size_t)layer * 16384);
        const float4* w2g = (const float4*)(g_W2p + (size_t)layer * 16384);
        float4* w1s = (float4*)wf1;
        float4* w2s = (float4*)wf2;
        #pragma unroll 4
        for (int i = tid; i < 4096; i += 256) { w1s[i] = __ldg(w1g + i); w2s[i] = __ldg(w2g + i); }
        if (tid < 128) {
            b1s[tid]  = __ldg(b1 + tid);
            b2s[tid]  = __ldg(b2 + tid);
            lngs[tid] = __ldg(lng + tid);
            lnbs[tid] = __ldg(lnb + tid);
        }
    }
    __syncthreads();

    const float* xid = pick_src(xs, xin);
    float* out = (osel == 0) ? g_bufA : g_bufB;

    float* rp0 = As + (wid * 16 + g) * AS_STRIDE;
    float* rp1 = rp0 + 8 * AS_STRIDE;

    float acc[16][4];

    for (int tile = blockIdx.x; tile < NT128; tile += gridDim.x) {
        int rowbase = tile * 128;
        int wrow = rowbase + wid * 16;

        {
            float* arow = As + wid * 16 * AS_STRIDE;
            #pragma unroll
            for (int i = 0; i < 16; i++) {
                float4 v = make_float4(0.f, 0.f, 0.f, 0.f);
                if (wrow + i < ROWS)
                    v = *(const float4*)(g_hbuf + (size_t)(wrow + i) * Dn + lane * 4);
                v.x = to_tf32(v.x); v.y = to_tf32(v.y);
                v.z = to_tf32(v.z); v.w = to_tf32(v.w);
                *(float4*)&arow[i * AS_STRIDE + lane * 4] = v;
            }
        }
        __syncwarp();

        #pragma unroll
        for (int nt = 0; nt < 16; nt++) { acc[nt][0]=acc[nt][1]=acc[nt][2]=acc[nt][3]=0.f; }
        #pragma unroll
        for (int kt = 0; kt < 16; kt++) {
            uint32_t a0 = __float_as_uint(rp0[kt*8 + tig]);
            uint32_t a1 = __float_as_uint(rp1[kt*8 + tig]);
            uint32_t a2 = __float_as_uint(rp0[kt*8 + tig + 4]);
            uint32_t a3 = __float_as_uint(rp1[kt*8 + tig + 4]);
            const float4* wfb = (const float4*)wf1 + kt * 8 * 32 + lane;
            #pragma unroll
            for (int np = 0; np < 8; np++) {
                float4 b = wfb[np * 32];
                mma_tf32(acc[2*np],   a0, a1, a2, a3, __float_as_uint(b.x), __float_as_uint(b.y));
                mma_tf32(acc[2*np+1], a0, a1, a2, a3, __float_as_uint(b.z), __float_as_uint(b.w));
            }
        }

        __syncwarp();
        #pragma unroll
        for (int nt = 0; nt < 16; nt++) {
            float2 bb = *(float2*)&b1s[nt*8 + tig*2];
            float2 lo, hi;
            lo.x = to_tf32(fmaxf(acc[nt][0] + bb.x, 0.f));
            lo.y = to_tf32(fmaxf(acc[nt][1] + bb.y, 0.f));
            hi.x = to_tf32(fmaxf(acc[nt][2] + bb.x, 0.f));
            hi.y = to_tf32(fmaxf(acc[nt][3] + bb.y, 0.f));
            *(float2*)&rp0[nt*8 + tig*2] = lo;
            *(float2*)&rp1[nt*8 + tig*2] = hi;
        }
        __syncwarp();

        #pragma unroll
        for (int nt = 0; nt < 16; nt++) { acc[nt][0]=acc[nt][1]=acc[nt][2]=acc[nt][3]=0.f; }
        #pragma unroll
        for (int kt = 0; kt < 16; kt++) {
            uint32_t a0 = __float_as_uint(rp0[kt*8 + tig]);
            uint32_t a1 = __float_as_uint(rp1[kt*8 + tig]);
            uint32_t a2 = __float_as_uint(rp0[kt*8 + tig + 4]);
            uint32_t a3 = __float_as_uint(rp1[kt*8 + tig + 4]);
            const float4* wfb = (const float4*)wf2 + kt * 8 * 32 + lane;
            #pragma unroll
            for (int np = 0; np < 8; np++) {
                float4 b = wfb[np * 32];
                mma_tf32(acc[2*np],   a0, a1, a2, a3, __float_as_uint(b.x), __float_as_uint(b.y));
                mma_tf32(acc[2*np+1], a0, a1, a2, a3, __float_as_uint(b.z), __float_as_uint(b.w));
            }
        }

        {
            int r0g = wrow + g, r1g = wrow + g + 8;
            bool v0 = r0g < ROWS, v1 = r1g < ROWS;
            const float* res0 = xid + (size_t)r0g * Dn;
            const float* res1 = xid + (size_t)r1g * Dn;
            float s0 = 0.f, ss0 = 0.f, s1 = 0.f, ss1 = 0.f;
            #pragma unroll
            for (int nt = 0; nt < 16; nt++) {
                int c = nt*8 + tig*2;
                float2 bb = *(float2*)&b2s[c];
                acc[nt][0] += bb.x; acc[nt][1] += bb.y;
                acc[nt][2] += bb.x; acc[nt][3] += bb.y;
                if (addRes) {
                    if (v0) { float2 rv = __ldg((const float2*)(res0 + c));
                              acc[nt][0] += rv.x; acc[nt][1] += rv.y; }
                    if (v1) { float2 rv = __ldg((const float2*)(res1 + c));
                              acc[nt][2] += rv.x; acc[nt][3] += rv.y; }
                }
                s0  += acc[nt][0] + acc[nt][1];
                ss0 += acc[nt][0]*acc[nt][0] + acc[nt][1]*acc[nt][1];
                s1  += acc[nt][2] + acc[nt][3];
                ss1 += acc[nt][2]*acc[nt][2] + acc[nt][3]*acc[nt][3];
            }
            s0  += __shfl_xor_sync(0xffffffffu, s0, 1);  s0  += __shfl_xor_sync(0xffffffffu, s0, 2);
            ss0 += __shfl_xor_sync(0xffffffffu, ss0, 1); ss0 += __shfl_xor_sync(0xffffffffu, ss0, 2);
            s1  += __shfl_xor_sync(0xffffffffu, s1, 1);  s1  += __shfl_xor_sync(0xffffffffu, s1, 2);
            ss1 += __shfl_xor_sync(0xffffffffu, ss1, 1); ss1 += __shfl_xor_sync(0xffffffffu, ss1, 2);
            float mu0 = s0 * (1.f/128.f), mu1 = s1 * (1.f/128.f);
            float iv0 = rsqrtf(ss0 * (1.f/128.f) - mu0*mu0 + LN_EPS);
            float iv1 = rsqrtf(ss1 * (1.f/128.f) - mu1*mu1 + LN_EPS);
            float* o0 = out + (size_t)r0g * Dn;
            float* o1 = out + (size_t)r1g * Dn;
            #pragma unroll
            for (int nt = 0; nt < 16; nt++) {
                int c = nt*8 + tig*2;
                float2 gg = *(float2*)&lngs[c];
                float2 bb = *(float2*)&lnbs[c];
                if (v0) {
                    float2 ov;
                    ov.x = (acc[nt][0] - mu0) * iv0 * gg.x + bb.x;
                    ov.y = (acc[nt][1] - mu0) * iv0 * gg.y + bb.y;
                    *(float2*)(o0 + c) = ov;
                }
                if (v1) {
                    float2 ov;
                    ov.x = (acc[nt][2] - mu1) * iv1 * gg.x + bb.x;
                    ov.y = (acc[nt][3] - mu1) * iv1 * gg.y + bb.y;
                    *(float2*)(o1 + c) = ov;
                }
            }
        }
        __syncwarp();
    }
}

// ---------------- readout + attention ----------------
__global__ void k_zero() { g_gvec[threadIdx.x] = 0.f; }

__global__ void k_readout(int xs) {
    const float* x = (xs == 0) ? g_bufA : g_bufB;
    int g = blockIdx.x;
    int chunk = blockIdx.y;
    int d = threadIdx.x;
    int i0 = chunk * 1563;
    int i1 = min(Nn, i0 + 1563);
    float s = 0.f;
    const float* base = x + (size_t)g * Nn * Dn + d;
    for (int i = i0; i < i1; i++) s += __ldg(base + (size_t)i * Dn);
    atomicAdd(&g_gvec[g * Dn + d], s);
}

__global__ void k_att(const float* __restrict__ w1, const float* __restrict__ w2,
                      float* __restrict__ out) {
    __shared__ float gm[Gn * Dn];
    __shared__ float sup[AHn * Gn];
    __shared__ float att[NEx * Gn];
    int tid = threadIdx.x;
    for (int i = tid; i < Gn * Dn; i += 256) gm[i] = g_gvec[i];
    __syncthreads();
    if (tid < AHn * Gn) {
        int ah = tid >> 2, gr = tid & 3;
        float s = 0.f;
        #pragma unroll 8
        for (int d = 0; d < Dn; d++) s = fmaf(__ldg(w1 + ah * Dn + d), gm[gr * Dn + d], s);
        sup[tid] = tanhf(s);
    }
    __syncthreads();
    if (tid < NEx * Gn) {
        int e = tid >> 2, gr = tid & 3;
        float s = 0.f;
        #pragma unroll 8
        for (int a = 0; a < AHn; a++) s = fmaf(__ldg(w2 + e * AHn + a), sup[a * 4 + gr], s);
        att[tid] = s;
    }
    __syncthreads();
    if (tid < NEx) {
        float m = -1e30f;
        #pragma unroll
        for (int gr = 0; gr < 4; gr++) m = fmaxf(m, att[tid * 4 + gr]);
        float ex[4]; float sum = 0.f;
        #pragma unroll
        for (int gr = 0; gr < 4; gr++) { ex[gr] = expf(att[tid * 4 + gr] - m); sum += ex[gr]; }
        float inv = 1.f / sum;
        #pragma unroll
        for (int gr = 0; gr < 4; gr++) att[tid * 4 + gr] = ex[gr] * inv;
    }
    __syncthreads();
    for (int o = tid; o < NEx * Dn; o += 256) {
        int e = o >> 7, d = o & 127;
        float s = 0.f;
        #pragma unroll
        for (int gr = 0; gr < 4; gr++) s = fmaf(att[e * 4 + gr], gm[gr * Dn + d], s);
        out[o] = s;
    }
}

// ---------------------------------------------------------------------------
extern "C" void kernel_launch(void* const* d_in, const int* in_sizes, int n_in,
                              void* d_out, int out_size) {
    const float* x0  = (const float*)d_in[0];
    const int*   ei  = (const int*)d_in[1];
    const float* Ws1 = (const float*)d_in[3];
    const float* bs1 = (const float*)d_in[4];
    const float* Ws2 = (const float*)d_in[5];
    const float* bs2 = (const float*)d_in[6];
    const float* lng = (const float*)d_in[7];
    const float* lnb = (const float*)d_in[8];
    const float* aw1 = (const float*)d_in[9];
    const float* aw2 = (const float*)d_in[10];
    float* out = (float*)d_out;

    cudaFuncSetAttribute(k_mlp_mma, cudaFuncAttributeMaxDynamicSharedMemorySize, SM_TOT);

    k_pack<<<(Ln * Dn * Dn + 255) / 256, 256>>>(Ws1, Ws2);

    // CSR build (once per launch; edge index is constant input)
    k_csr_zero<<<NB_SCAN, 256>>>();
    k_csr_count<<<EDGES / 256, 256>>>(ei);
    k_scan_block<<<NB_SCAN, 256>>>();
    k_scan_top<<<1, 1024>>>();
    k_scan_add<<<NB_SCAN, 256>>>();
    k_csr_fill<<<EDGES / 256, 256>>>(ei);

    int xs = -1;  // -1: input, 0: bufA, 1: bufB
    for (int l = 0; l < Ln; l++) {
        k_agg<<<ROWS / 8, 256>>>(x0, xs);     // h = x + sum_neighbors
        int osel = (l == 1) ? 1 : 0;
        k_mlp_mma<<<148, 256, SM_TOT>>>(x0, xs, l,
                                        bs1 + l * Dn, bs2 + l * Dn,
                                        lng + l * Dn, lnb + l * Dn,
                                        (l < Ln - 1) ? 1 : 0, osel);
        xs = osel;
    }
    k_zero<<<1, Gn * Dn>>>();
    k_readout<<<dim3(Gn, 32), Dn>>>(xs);
    k_att<<<1, 256>>>(aw1, aw2, out);
}